// round 1
// baseline (speedup 1.0000x reference)
#include <cuda_runtime.h>
#include <math.h>

// Problem constants
#define B_   4
#define T_   2048
#define C_   2048
#define H_   16
#define D_   128
#define M_   (B_ * T_)        // 8192 rows of x
#define N3_  (3 * C_)         // 6144 qkv cols
#define BH_  (B_ * H_)        // 64 (batch*heads)

// -------------------- scratch (device globals; no allocation) ---------------
__device__ float g_qkv[(size_t)M_ * N3_];            // [8192,6144]  201 MB
__device__ float g_q[(size_t)BH_ * T_ * D_];         // [bh,T,D]      67 MB
__device__ float g_k[(size_t)BH_ * T_ * D_];
__device__ float g_v[(size_t)BH_ * T_ * D_];
__device__ float g_s[(size_t)BH_ * T_ * T_];         // scores/probs 1.07 GB
__device__ float g_o[(size_t)BH_ * T_ * D_];         // attn out [bh,T,D]
__device__ float g_attn[(size_t)M_ * C_];            // merged [8192,2048]
__device__ float g_cos[T_ * 64];
__device__ float g_sin[T_ * 64];

// -------------------- RoPE cos/sin table (fp64 phase for accuracy) ----------
__global__ void rope_table_kernel() {
    int t = blockIdx.x;        // 0..T-1
    int p = threadIdx.x;       // 0..63
    double freq  = pow(10000.0, -(double)p / 64.0);
    double phase = (double)t * freq;
    g_cos[t * 64 + p] = (float)cos(phase);
    g_sin[t * 64 + p] = (float)sin(phase);
}

// -------------------- generic fp32 SGEMM: C = A[M,K] @ B[K,N] (+bias) -------
// 128x128 tile, BK=8, 256 threads, 8x8 per-thread microtile.
__global__ __launch_bounds__(256)
void sgemm128_kernel(const float* __restrict__ A, const float* __restrict__ Bm,
                     float* __restrict__ Cm, int Mdim, int Ndim, int Kdim,
                     const float* __restrict__ bias) {
    __shared__ float As[8][128];
    __shared__ float Bs[8][128];

    int tid = threadIdx.x;
    int tx = tid & 15;          // 0..15  -> 8 cols each
    int ty = tid >> 4;          // 0..15  -> 8 rows each
    int bx = blockIdx.x, by = blockIdx.y;

    const float* Ablk = A + (size_t)by * 128 * Kdim;
    const float* Bblk = Bm + (size_t)bx * 128;

    // A tile load mapping: 128 rows x 8 cols, one float4 per thread
    int a_row = tid >> 1;            // 0..127
    int a_col = (tid & 1) * 4;       // 0 or 4
    // B tile load mapping: 8 rows x 128 cols, one float4 per thread
    int b_row = tid >> 5;            // 0..7
    int b_col = (tid & 31) * 4;      // 0..124

    float acc[8][8];
#pragma unroll
    for (int i = 0; i < 8; i++)
#pragma unroll
        for (int j = 0; j < 8; j++) acc[i][j] = 0.0f;

    for (int k0 = 0; k0 < Kdim; k0 += 8) {
        float4 av = *(const float4*)&Ablk[(size_t)a_row * Kdim + k0 + a_col];
        float4 bv = *(const float4*)&Bblk[(size_t)(k0 + b_row) * Ndim + b_col];
        As[a_col + 0][a_row] = av.x;
        As[a_col + 1][a_row] = av.y;
        As[a_col + 2][a_row] = av.z;
        As[a_col + 3][a_row] = av.w;
        *(float4*)&Bs[b_row][b_col] = bv;
        __syncthreads();

#pragma unroll
        for (int kk = 0; kk < 8; kk++) {
            float a[8], b[8];
            *(float4*)(a + 0) = *(const float4*)&As[kk][ty * 8 + 0];
            *(float4*)(a + 4) = *(const float4*)&As[kk][ty * 8 + 4];
            *(float4*)(b + 0) = *(const float4*)&Bs[kk][tx * 8 + 0];
            *(float4*)(b + 4) = *(const float4*)&Bs[kk][tx * 8 + 4];
#pragma unroll
            for (int i = 0; i < 8; i++)
#pragma unroll
                for (int j = 0; j < 8; j++) acc[i][j] += a[i] * b[j];
        }
        __syncthreads();
    }

#pragma unroll
    for (int i = 0; i < 8; i++) {
        int row = by * 128 + ty * 8 + i;
        int colbase = bx * 128 + tx * 8;
        float4 o0, o1;
        if (bias) {
            o0.x = acc[i][0] + bias[colbase + 0];
            o0.y = acc[i][1] + bias[colbase + 1];
            o0.z = acc[i][2] + bias[colbase + 2];
            o0.w = acc[i][3] + bias[colbase + 3];
            o1.x = acc[i][4] + bias[colbase + 4];
            o1.y = acc[i][5] + bias[colbase + 5];
            o1.z = acc[i][6] + bias[colbase + 6];
            o1.w = acc[i][7] + bias[colbase + 7];
        } else {
            o0.x = acc[i][0]; o0.y = acc[i][1]; o0.z = acc[i][2]; o0.w = acc[i][3];
            o1.x = acc[i][4]; o1.y = acc[i][5]; o1.z = acc[i][6]; o1.w = acc[i][7];
        }
        *(float4*)&Cm[(size_t)row * Ndim + colbase + 0] = o0;
        *(float4*)&Cm[(size_t)row * Ndim + colbase + 4] = o1;
    }
}

// -------------------- RoPE + head split: qkv -> q,k,v in [bh,T,D] -----------
__global__ void rope_split_kernel() {
    int row = blockIdx.x;      // 0..8191  (b*T + t)
    int h   = blockIdx.y;      // 0..15
    int d   = threadIdx.x;     // 0..127
    int b = row >> 11;
    int t = row & (T_ - 1);

    const float* base = &g_qkv[(size_t)row * N3_];
    float qv = base[h * D_ + d];
    float kv = base[C_ + h * D_ + d];
    float vv = base[2 * C_ + h * D_ + d];

    int p = d & 63;
    float c = g_cos[t * 64 + p];
    float s = g_sin[t * 64 + p];
    float qp, kp;
    if (d < 64) {
        qp = -base[h * D_ + d + 64];
        kp = -base[C_ + h * D_ + d + 64];
    } else {
        qp = base[h * D_ + d - 64];
        kp = base[C_ + h * D_ + d - 64];
    }

    size_t oidx = ((size_t)(b * H_ + h) * T_ + t) * D_ + d;
    g_q[oidx] = qv * c + qp * s;
    g_k[oidx] = kv * c + kp * s;
    g_v[oidx] = vv;
}

// -------------------- scores: lower-triangular 64x64 tiles only -------------
// S[bh,i,j] = scale * sum_d Q[bh,i,d]*K[bh,j,d]; dynamic smem (2*128*68 fp32)
__global__ __launch_bounds__(256)
void score_kernel() {
    extern __shared__ float sm[];
    float* Qs = sm;                 // [128][68] transposed: Qs[d][row]
    float* Ks = sm + 128 * 68;      // [128][68]

    int bh = blockIdx.y;
    int lt = blockIdx.x;            // 0..527 lower-tri tile id
    int ti = (int)((sqrtf(8.0f * (float)lt + 1.0f) - 1.0f) * 0.5f);
    while ((ti + 1) * (ti + 2) / 2 <= lt) ti++;
    while (ti * (ti + 1) / 2 > lt) ti--;
    int tj = lt - ti * (ti + 1) / 2;   // tj <= ti (causal)

    const float* Qb = g_q + (size_t)bh * T_ * D_ + (size_t)ti * 64 * D_;
    const float* Kb = g_k + (size_t)bh * T_ * D_ + (size_t)tj * 64 * D_;

    int tid = threadIdx.x;
    int lrow    = tid & 63;     // 0..63
    int base_d4 = tid >> 6;     // 0..3

#pragma unroll
    for (int cch = 0; cch < 8; cch++) {
        int d4 = base_d4 + cch * 4;   // 0..31
        float4 qv = *(const float4*)&Qb[(size_t)lrow * D_ + d4 * 4];
        float4 kv = *(const float4*)&Kb[(size_t)lrow * D_ + d4 * 4];
        Qs[(d4 * 4 + 0) * 68 + lrow] = qv.x;
        Qs[(d4 * 4 + 1) * 68 + lrow] = qv.y;
        Qs[(d4 * 4 + 2) * 68 + lrow] = qv.z;
        Qs[(d4 * 4 + 3) * 68 + lrow] = qv.w;
        Ks[(d4 * 4 + 0) * 68 + lrow] = kv.x;
        Ks[(d4 * 4 + 1) * 68 + lrow] = kv.y;
        Ks[(d4 * 4 + 2) * 68 + lrow] = kv.z;
        Ks[(d4 * 4 + 3) * 68 + lrow] = kv.w;
    }
    __syncthreads();

    int tx = tid & 15, ty = tid >> 4;
    float acc[4][4];
#pragma unroll
    for (int i = 0; i < 4; i++)
#pragma unroll
        for (int j = 0; j < 4; j++) acc[i][j] = 0.0f;

#pragma unroll 4
    for (int d = 0; d < 128; d++) {
        float4 a = *(const float4*)&Qs[d * 68 + ty * 4];
        float4 b = *(const float4*)&Ks[d * 68 + tx * 4];
        acc[0][0] += a.x * b.x; acc[0][1] += a.x * b.y; acc[0][2] += a.x * b.z; acc[0][3] += a.x * b.w;
        acc[1][0] += a.y * b.x; acc[1][1] += a.y * b.y; acc[1][2] += a.y * b.z; acc[1][3] += a.y * b.w;
        acc[2][0] += a.z * b.x; acc[2][1] += a.z * b.y; acc[2][2] += a.z * b.z; acc[2][3] += a.z * b.w;
        acc[3][0] += a.w * b.x; acc[3][1] += a.w * b.y; acc[3][2] += a.w * b.z; acc[3][3] += a.w * b.w;
    }

    const float scale = 0.08838834764831845f;   // 1/sqrt(128)
    float* Srow = g_s + (size_t)bh * T_ * T_;
#pragma unroll
    for (int i = 0; i < 4; i++) {
        int gi = ti * 64 + ty * 4 + i;
        int gj = tj * 64 + tx * 4;
        float4 o;
        o.x = acc[i][0] * scale; o.y = acc[i][1] * scale;
        o.z = acc[i][2] * scale; o.w = acc[i][3] * scale;
        *(float4*)&Srow[(size_t)gi * T_ + gj] = o;
    }
}

// -------------------- causal softmax per row, zero-pad to 64 boundary -------
__global__ __launch_bounds__(256)
void softmax_kernel() {
    int bh = blockIdx.y;
    int i  = blockIdx.x;
    float* row = g_s + (size_t)bh * T_ * T_ + (size_t)i * T_;
    int len = i + 1;
    int tid = threadIdx.x;
    __shared__ float red[256];

    float m = -INFINITY;
    for (int j = tid; j < len; j += 256) m = fmaxf(m, row[j]);
    red[tid] = m; __syncthreads();
    for (int s = 128; s > 0; s >>= 1) {
        if (tid < s) red[tid] = fmaxf(red[tid], red[tid + s]);
        __syncthreads();
    }
    m = red[0];
    __syncthreads();

    float ssum = 0.0f;
    for (int j = tid; j < len; j += 256) ssum += expf(row[j] - m);
    red[tid] = ssum; __syncthreads();
    for (int s = 128; s > 0; s >>= 1) {
        if (tid < s) red[tid] += red[tid + s];
        __syncthreads();
    }
    float inv = 1.0f / red[0];

    for (int j = tid; j < len; j += 256) row[j] = expf(row[j] - m) * inv;
    // zero-pad (len, tile boundary) so the AV GEMM K-loop is branch-free
    int pad_end = ((i >> 6) + 1) << 6;
    for (int j = len + tid; j < pad_end; j += 256) row[j] = 0.0f;
}

// -------------------- AV: O[bh,i,d] = sum_j P[bh,i,j] V[bh,j,d] -------------
// q-tile 64 rows, N=128 (full D), BK=16; K-loop clipped at causal boundary.
__global__ __launch_bounds__(256)
void av_kernel() {
    __shared__ float Ps[16][68];    // transposed: Ps[kk][row]
    __shared__ float Vs[16][128];

    int bh = blockIdx.y;
    int ti = blockIdx.x;            // 0..31
    int tid = threadIdx.x;
    int tx = tid & 15, ty = tid >> 4;

    const float* Pb = g_s + (size_t)bh * T_ * T_ + (size_t)ti * 64 * T_;
    const float* Vb = g_v + (size_t)bh * T_ * D_;
    int kmax = (ti + 1) * 64;

    int prow = tid >> 2;            // 0..63
    int pj4  = tid & 3;             // 0..3
    int vrow = tid >> 5;            // 0..7
    int vcol = (tid & 31) * 4;      // 0..124

    float acc[4][8];
#pragma unroll
    for (int i = 0; i < 4; i++)
#pragma unroll
        for (int j = 0; j < 8; j++) acc[i][j] = 0.0f;

    for (int k0 = 0; k0 < kmax; k0 += 16) {
        float4 pv = *(const float4*)&Pb[(size_t)prow * T_ + k0 + pj4 * 4];
        Ps[pj4 * 4 + 0][prow] = pv.x;
        Ps[pj4 * 4 + 1][prow] = pv.y;
        Ps[pj4 * 4 + 2][prow] = pv.z;
        Ps[pj4 * 4 + 3][prow] = pv.w;
#pragma unroll
        for (int r = 0; r < 2; r++) {
            int vr = vrow + r * 8;
            *(float4*)&Vs[vr][vcol] =
                *(const float4*)&Vb[(size_t)(k0 + vr) * D_ + vcol];
        }
        __syncthreads();

#pragma unroll
        for (int kk = 0; kk < 16; kk++) {
            float4 a  = *(const float4*)&Ps[kk][ty * 4];
            float4 b0 = *(const float4*)&Vs[kk][tx * 8 + 0];
            float4 b1 = *(const float4*)&Vs[kk][tx * 8 + 4];
            float av_[4] = {a.x, a.y, a.z, a.w};
            float bv_[8] = {b0.x, b0.y, b0.z, b0.w, b1.x, b1.y, b1.z, b1.w};
#pragma unroll
            for (int i = 0; i < 4; i++)
#pragma unroll
                for (int j = 0; j < 8; j++) acc[i][j] += av_[i] * bv_[j];
        }
        __syncthreads();
    }

    float* Ob = g_o + (size_t)bh * T_ * D_;
#pragma unroll
    for (int i = 0; i < 4; i++) {
        int row = ti * 64 + ty * 4 + i;
        float4 o0, o1;
        o0.x = acc[i][0]; o0.y = acc[i][1]; o0.z = acc[i][2]; o0.w = acc[i][3];
        o1.x = acc[i][4]; o1.y = acc[i][5]; o1.z = acc[i][6]; o1.w = acc[i][7];
        *(float4*)&Ob[(size_t)row * D_ + tx * 8 + 0] = o0;
        *(float4*)&Ob[(size_t)row * D_ + tx * 8 + 4] = o1;
    }
}

// -------------------- merge heads: [bh,T,D] -> [b*T, C] ---------------------
__global__ void transpose_o_kernel() {
    int row = blockIdx.x;     // 0..8191 (b*T + t)
    int h   = blockIdx.y;     // 0..15
    int d   = threadIdx.x;    // 0..127
    int b = row >> 11;
    int t = row & (T_ - 1);
    g_attn[(size_t)row * C_ + h * D_ + d] =
        g_o[((size_t)(b * H_ + h) * T_ + t) * D_ + d];
}

// -------------------- launch ------------------------------------------------
extern "C" void kernel_launch(void* const* d_in, const int* in_sizes, int n_in,
                              void* d_out, int out_size) {
    const float* x      = (const float*)d_in[0];
    const float* w_qkv  = (const float*)d_in[1];
    const float* w_proj = (const float*)d_in[2];
    const float* b_proj = (const float*)d_in[3];
    float* out = (float*)d_out;

    float *p_qkv, *p_attn;
    cudaGetSymbolAddress((void**)&p_qkv, g_qkv);
    cudaGetSymbolAddress((void**)&p_attn, g_attn);

    int score_smem = 2 * 128 * 68 * sizeof(float);   // 69632 B
    cudaFuncSetAttribute(score_kernel,
                         cudaFuncAttributeMaxDynamicSharedMemorySize, score_smem);

    rope_table_kernel<<<T_, 64>>>();

    // QKV GEMM: [8192,2048] @ [2048,6144]
    sgemm128_kernel<<<dim3(N3_ / 128, M_ / 128), 256>>>(
        x, w_qkv, p_qkv, M_, N3_, C_, nullptr);

    rope_split_kernel<<<dim3(M_, H_), D_>>>();

    score_kernel<<<dim3(528, BH_), 256, score_smem>>>();

    softmax_kernel<<<dim3(T_, BH_), 256>>>();

    av_kernel<<<dim3(T_ / 64, BH_), 256>>>();

    transpose_o_kernel<<<dim3(M_, H_), D_>>>();

    // proj GEMM + bias: [8192,2048] @ [2048,2048]
    sgemm128_kernel<<<dim3(C_ / 128, M_ / 128), 256>>>(
        p_attn, w_proj, out, M_, C_, C_, b_proj);
}

// round 5
// speedup vs baseline: 2.4680x; 2.4680x over previous
#include <cuda_runtime.h>
#include <cuda_bf16.h>
#include <math.h>
#include <stdint.h>

#define B_   4
#define T_   2048
#define C_   2048
#define H_   16
#define D_   128
#define M_   (B_ * T_)        // 8192
#define N3_  (3 * C_)         // 6144
#define BH_  (B_ * H_)        // 64

typedef __nv_bfloat16 bf16;

// ---------------------------------------------------------------------------
// scratch (device globals; no allocation)  — total ~1.75 GB
// ---------------------------------------------------------------------------
__device__ float g_qkv[(size_t)M_ * N3_];            // 201 MB (dead after rope
                                                     //  -> reused for ah/al)
__device__ bf16  g_xh [(size_t)M_ * C_];
__device__ bf16  g_xl [(size_t)M_ * C_];
__device__ bf16  g_wqh[(size_t)N3_ * C_];            // w_qkv^T split [6144,2048]
__device__ bf16  g_wql[(size_t)N3_ * C_];
__device__ bf16  g_wph[(size_t)C_ * C_];             // w_proj^T split
__device__ bf16  g_wpl[(size_t)C_ * C_];
__device__ bf16  g_q2h[(size_t)BH_ * T_ * D_];       // rope'd q split [bh,T,D]
__device__ bf16  g_q2l[(size_t)BH_ * T_ * D_];
__device__ bf16  g_k2h[(size_t)BH_ * T_ * D_];
__device__ bf16  g_k2l[(size_t)BH_ * T_ * D_];
__device__ float g_v  [(size_t)BH_ * T_ * D_];
__device__ bf16  g_vth[(size_t)BH_ * D_ * T_];       // v^T split [bh,D,T]
__device__ bf16  g_vtl[(size_t)BH_ * D_ * T_];
// scores fp32; softmax rewrites each row IN PLACE as [ph: T bf16 | pl: T bf16]
__device__ float g_s  [(size_t)BH_ * T_ * T_];       // 1.07 GB
__device__ float g_o  [(size_t)BH_ * T_ * D_];       // attn out [bh,T,D]
__device__ float g_cos[T_ * 64];
__device__ float g_sin[T_ * 64];

// ---------------------------------------------------------------------------
// helpers
// ---------------------------------------------------------------------------
__device__ __forceinline__ uint32_t smem_u32(const void* p) {
    uint32_t a;
    asm("{ .reg .u64 t; cvta.to.shared.u64 t, %1; cvt.u32.u64 %0, t; }"
        : "=r"(a) : "l"(p));
    return a;
}

#define CP_COMMIT() asm volatile("cp.async.commit_group;" ::: "memory")
#define CP_WAIT(n)  asm volatile("cp.async.wait_group %0;" :: "n"(n) : "memory")

__device__ __forceinline__ void cp16(uint32_t saddr, const void* g) {
    asm volatile("cp.async.cg.shared.global [%0], [%1], 16;"
                 :: "r"(saddr), "l"(g) : "memory");
}

__device__ __forceinline__ void ldm_x4(uint32_t a, uint32_t& r0, uint32_t& r1,
                                       uint32_t& r2, uint32_t& r3) {
    asm volatile("ldmatrix.sync.aligned.m8n8.x4.shared.b16 {%0,%1,%2,%3}, [%4];"
                 : "=r"(r0), "=r"(r1), "=r"(r2), "=r"(r3) : "r"(a));
}

__device__ __forceinline__ void mma16816(float* c, const uint32_t* a,
                                         uint32_t b0, uint32_t b1) {
    asm volatile(
        "mma.sync.aligned.m16n8k16.row.col.f32.bf16.bf16.f32 "
        "{%0,%1,%2,%3}, {%4,%5,%6,%7}, {%8,%9}, {%0,%1,%2,%3};"
        : "+f"(c[0]), "+f"(c[1]), "+f"(c[2]), "+f"(c[3])
        : "r"(a[0]), "r"(a[1]), "r"(a[2]), "r"(a[3]), "r"(b0), "r"(b1));
}

// split fp32 -> (hi, lo) bf16
__device__ __forceinline__ void splitb(float v, bf16& h, bf16& l) {
    bf16 hb = __float2bfloat16(v);
    h = hb;
    l = __float2bfloat16(v - __bfloat162float(hb));
}

// ---------------------------------------------------------------------------
// GEMM core: C[128,128] = A[128,K] * B[128,K]^T  (both K-major, split bf16)
// 256 threads, 8 warps (warp tile 32x64), BK=32, double buffered cp.async.
// 3 mma passes: Ah*Bh + Ah*Bl + Al*Bh.
// ---------------------------------------------------------------------------
#define BK      32
#define KS      40                      // smem row stride (bf16 elems) = 80 B
#define TILE_B  (128 * KS * 2)          // 10240 B per tile
#define STAGE_B (4 * TILE_B)            // Ah, Al, Bh, Bl
#define GEMM_SMEM (2 * STAGE_B)         // 81920 B

__device__ __forceinline__ void prefetch_chunk(
    uint32_t sstage, const bf16* Ah, const bf16* Al,
    const bf16* Bh, const bf16* Bl, int lda, int ldb, int k0)
{
    int tid = threadIdx.x;
#pragma unroll
    for (int t2 = 0; t2 < 2; t2++) {
        int task = tid + t2 * 256;          // 0..511
        int row = task >> 2, seg = task & 3;
        uint32_t soff = (uint32_t)(row * (KS * 2) + seg * 16);
        size_t aoff = (size_t)row * lda + k0 + seg * 8;
        size_t boff = (size_t)row * ldb + k0 + seg * 8;
        cp16(sstage + 0 * TILE_B + soff, Ah + aoff);
        cp16(sstage + 1 * TILE_B + soff, Al + aoff);
        cp16(sstage + 2 * TILE_B + soff, Bh + boff);
        cp16(sstage + 3 * TILE_B + soff, Bl + boff);
    }
}

__device__ __forceinline__ void compute_stage(uint32_t sstage,
                                              float acc[2][8][4]) {
    int lane = threadIdx.x & 31, wid = threadIdx.x >> 5;
    int wm = wid >> 1;                  // 0..3 (m offset wm*32)
    int wn = wid & 1;                   // 0..1 (n offset wn*64)
    uint32_t Ahs = sstage + 0 * TILE_B, Als = sstage + 1 * TILE_B;
    uint32_t Bhs = sstage + 2 * TILE_B, Bls = sstage + 3 * TILE_B;

    int arow  = wm * 32 + (lane & 15);
    int acolg = (lane >> 4) * 8;
    int brow  = wn * 64 + ((lane >> 4) & 1) * 8 + (lane & 7);
    int bcolg = ((lane >> 3) & 1) * 8;

#pragma unroll
    for (int ks = 0; ks < 2; ks++) {
        int kb = ks * 16;
        uint32_t a[2][4], bh[4][4], bl[4][4];

        // pass 1: Ah * Bh
#pragma unroll
        for (int mt = 0; mt < 2; mt++)
            ldm_x4(Ahs + (uint32_t)((arow + mt * 16) * (KS * 2) + (kb + acolg) * 2),
                   a[mt][0], a[mt][1], a[mt][2], a[mt][3]);
#pragma unroll
        for (int np = 0; np < 4; np++)
            ldm_x4(Bhs + (uint32_t)((brow + np * 16) * (KS * 2) + (kb + bcolg) * 2),
                   bh[np][0], bh[np][1], bh[np][2], bh[np][3]);
#pragma unroll
        for (int mt = 0; mt < 2; mt++)
#pragma unroll
            for (int np = 0; np < 4; np++) {
                mma16816(acc[mt][np * 2 + 0], a[mt], bh[np][0], bh[np][1]);
                mma16816(acc[mt][np * 2 + 1], a[mt], bh[np][2], bh[np][3]);
            }

        // pass 2: Ah * Bl
#pragma unroll
        for (int np = 0; np < 4; np++)
            ldm_x4(Bls + (uint32_t)((brow + np * 16) * (KS * 2) + (kb + bcolg) * 2),
                   bl[np][0], bl[np][1], bl[np][2], bl[np][3]);
#pragma unroll
        for (int mt = 0; mt < 2; mt++)
#pragma unroll
            for (int np = 0; np < 4; np++) {
                mma16816(acc[mt][np * 2 + 0], a[mt], bl[np][0], bl[np][1]);
                mma16816(acc[mt][np * 2 + 1], a[mt], bl[np][2], bl[np][3]);
            }

        // pass 3: Al * Bh
#pragma unroll
        for (int mt = 0; mt < 2; mt++)
            ldm_x4(Als + (uint32_t)((arow + mt * 16) * (KS * 2) + (kb + acolg) * 2),
                   a[mt][0], a[mt][1], a[mt][2], a[mt][3]);
#pragma unroll
        for (int mt = 0; mt < 2; mt++)
#pragma unroll
            for (int np = 0; np < 4; np++) {
                mma16816(acc[mt][np * 2 + 0], a[mt], bh[np][0], bh[np][1]);
                mma16816(acc[mt][np * 2 + 1], a[mt], bh[np][2], bh[np][3]);
            }
    }
}

__device__ __forceinline__ void gemm_main(
    const bf16* Ah, const bf16* Al, const bf16* Bh, const bf16* Bl,
    int lda, int ldb, int nchunk, char* dsm, float acc[2][8][4])
{
    uint32_t s0 = smem_u32(dsm);
    prefetch_chunk(s0, Ah, Al, Bh, Bl, lda, ldb, 0);
    CP_COMMIT();
    for (int ic = 0; ic < nchunk; ic++) {
        if (ic + 1 < nchunk) {
            prefetch_chunk(s0 + (uint32_t)((ic + 1) & 1) * STAGE_B,
                           Ah, Al, Bh, Bl, lda, ldb, (ic + 1) * BK);
            CP_COMMIT();
            CP_WAIT(1);
        } else {
            CP_WAIT(0);
        }
        __syncthreads();
        compute_stage(s0 + (uint32_t)(ic & 1) * STAGE_B, acc);
        __syncthreads();
    }
}

__device__ __forceinline__ void store_c(float acc[2][8][4], float* C, int ldc,
                                        float scale, const float* bias) {
    int lane = threadIdx.x & 31, wid = threadIdx.x >> 5;
    int wm = wid >> 1, wn = wid & 1;
#pragma unroll
    for (int mt = 0; mt < 2; mt++) {
        int r0 = wm * 32 + mt * 16 + (lane >> 2);
#pragma unroll
        for (int nt = 0; nt < 8; nt++) {
            int c0 = wn * 64 + nt * 8 + (lane & 3) * 2;
            float2 v0, v1;
            v0.x = acc[mt][nt][0] * scale; v0.y = acc[mt][nt][1] * scale;
            v1.x = acc[mt][nt][2] * scale; v1.y = acc[mt][nt][3] * scale;
            if (bias) {
                v0.x += bias[c0]; v0.y += bias[c0 + 1];
                v1.x += bias[c0]; v1.y += bias[c0 + 1];
            }
            *(float2*)&C[(size_t)r0 * ldc + c0] = v0;
            *(float2*)&C[(size_t)(r0 + 8) * ldc + c0] = v1;
        }
    }
}

// ---------------------------------------------------------------------------
// GEMM kernels
// ---------------------------------------------------------------------------
__global__ __launch_bounds__(256)
void lin_gemm_kernel(const bf16* __restrict__ Ah, const bf16* __restrict__ Al,
                     const bf16* __restrict__ Bh, const bf16* __restrict__ Bl,
                     float* __restrict__ Cm, int N, int K,
                     const float* __restrict__ bias) {
    extern __shared__ char dsm[];
    float acc[2][8][4];
#pragma unroll
    for (int i = 0; i < 2; i++)
#pragma unroll
        for (int j = 0; j < 8; j++)
#pragma unroll
            for (int q = 0; q < 4; q++) acc[i][j][q] = 0.0f;
    size_t ao = (size_t)blockIdx.y * 128 * K;
    size_t bo = (size_t)blockIdx.x * 128 * K;
    gemm_main(Ah + ao, Al + ao, Bh + bo, Bl + bo, K, K, K / BK, dsm, acc);
    store_c(acc, Cm + (size_t)blockIdx.y * 128 * N + blockIdx.x * 128, N,
            1.0f, bias ? bias + blockIdx.x * 128 : nullptr);
}

__global__ __launch_bounds__(256)
void score_gemm_kernel() {
    extern __shared__ char dsm[];
    float acc[2][8][4];
#pragma unroll
    for (int i = 0; i < 2; i++)
#pragma unroll
        for (int j = 0; j < 8; j++)
#pragma unroll
            for (int q = 0; q < 4; q++) acc[i][j][q] = 0.0f;
    int bh = blockIdx.y;
    int lt = blockIdx.x;                     // 0..135 lower-tri 128-tile id
    int ti = (int)((sqrtf(8.0f * (float)lt + 1.0f) - 1.0f) * 0.5f);
    while ((ti + 1) * (ti + 2) / 2 <= lt) ti++;
    while (ti * (ti + 1) / 2 > lt) ti--;
    int tj = lt - ti * (ti + 1) / 2;
    size_t qo = (size_t)bh * T_ * D_ + (size_t)ti * 128 * D_;
    size_t ko = (size_t)bh * T_ * D_ + (size_t)tj * 128 * D_;
    gemm_main(g_q2h + qo, g_q2l + qo, g_k2h + ko, g_k2l + ko, D_, D_, D_ / BK,
              dsm, acc);
    float* Cp = g_s + (size_t)bh * T_ * T_ + (size_t)ti * 128 * T_ + tj * 128;
    store_c(acc, Cp, T_, 0.08838834764831845f, nullptr);
}

__global__ __launch_bounds__(256)
void av_gemm_kernel() {
    extern __shared__ char dsm[];
    float acc[2][8][4];
#pragma unroll
    for (int i = 0; i < 2; i++)
#pragma unroll
        for (int j = 0; j < 8; j++)
#pragma unroll
            for (int q = 0; q < 4; q++) acc[i][j][4 - 4 + q] = 0.0f;
    int bh = blockIdx.y;
    int ti = blockIdx.x;                     // 0..15
    // probs live in-place inside g_s rows: [ph: T bf16 | pl: T bf16] per row
    const bf16* ph = (const bf16*)(g_s + (size_t)bh * T_ * T_ +
                                   (size_t)ti * 128 * T_);
    const bf16* pl = ph + T_;
    const int lda = 2 * T_;                  // bf16 elems per fp32 row
    const bf16* vh = g_vth + (size_t)bh * D_ * T_;
    const bf16* vl = g_vtl + (size_t)bh * D_ * T_;
    gemm_main(ph, pl, vh, vl, lda, T_, (ti + 1) * 4, dsm, acc);
    store_c(acc, g_o + (size_t)bh * T_ * D_ + (size_t)ti * 128 * D_, D_,
            1.0f, nullptr);
}

// ---------------------------------------------------------------------------
// prep / elementwise kernels
// ---------------------------------------------------------------------------
__global__ void rope_table_kernel() {
    int t = blockIdx.x, p = threadIdx.x;
    double freq  = pow(10000.0, -(double)p / 64.0);
    double phase = (double)t * freq;
    g_cos[t * 64 + p] = (float)cos(phase);
    g_sin[t * 64 + p] = (float)sin(phase);
}

__global__ void split_x_kernel(const float* __restrict__ x) {
    size_t i = (size_t)blockIdx.x * blockDim.x + threadIdx.x;
    splitb(x[i], g_xh[i], g_xl[i]);
}

// transpose + split: W[K,N] -> Th/Tl [N,K] bf16
__global__ void wtrans_kernel(const float* __restrict__ W, bf16* __restrict__ Th,
                              bf16* __restrict__ Tl, int K, int N) {
    __shared__ float tile[32][33];
    int nb = blockIdx.x * 32, kb = blockIdx.y * 32;
    int tx = threadIdx.x, ty = threadIdx.y;    // 32 x 8
#pragma unroll
    for (int r = 0; r < 32; r += 8)
        tile[ty + r][tx] = W[(size_t)(kb + ty + r) * N + nb + tx];
    __syncthreads();
#pragma unroll
    for (int r = 0; r < 32; r += 8) {
        float v = tile[tx][ty + r];
        size_t o = (size_t)(nb + ty + r) * K + kb + tx;
        splitb(v, Th[o], Tl[o]);
    }
}

__global__ void rope_split_kernel() {
    int row = blockIdx.x, h = blockIdx.y, d = threadIdx.x;
    int b = row >> 11, t = row & (T_ - 1);
    const float* base = &g_qkv[(size_t)row * N3_];
    float qv = base[h * D_ + d];
    float kv = base[C_ + h * D_ + d];
    float vv = base[2 * C_ + h * D_ + d];
    int p = d & 63;
    float c = g_cos[t * 64 + p];
    float s = g_sin[t * 64 + p];
    float qp, kp;
    if (d < 64) {
        qp = -base[h * D_ + d + 64];
        kp = -base[C_ + h * D_ + d + 64];
    } else {
        qp = base[h * D_ + d - 64];
        kp = base[C_ + h * D_ + d - 64];
    }
    float qr = qv * c + qp * s;
    float kr = kv * c + kp * s;
    size_t o = ((size_t)(b * H_ + h) * T_ + t) * D_ + d;
    splitb(qr, g_q2h[o], g_q2l[o]);
    splitb(kr, g_k2h[o], g_k2l[o]);
    g_v[o] = vv;
}

// v [bh,T,D] -> v^T split [bh,D,T] bf16
__global__ void vtrans_kernel() {
    __shared__ float tile[32][33];
    int bh = blockIdx.z;
    int tb = blockIdx.x * 32;   // token
    int db = blockIdx.y * 32;   // dim
    int tx = threadIdx.x, ty = threadIdx.y;
    const float* V = g_v + (size_t)bh * T_ * D_;
#pragma unroll
    for (int r = 0; r < 32; r += 8)
        tile[ty + r][tx] = V[(size_t)(tb + ty + r) * D_ + db + tx];
    __syncthreads();
    bf16* oh = g_vth + (size_t)bh * D_ * T_;
    bf16* ol = g_vtl + (size_t)bh * D_ * T_;
#pragma unroll
    for (int r = 0; r < 32; r += 8) {
        float v = tile[tx][ty + r];
        size_t o = (size_t)(db + ty + r) * T_ + tb + tx;
        splitb(v, oh[o], ol[o]);
    }
}

// softmax: stage fp32 row in smem, then rewrite row IN PLACE as split bf16
// probs [ph: T | pl: T], zero-padded to the 128-tile boundary.
__global__ __launch_bounds__(256)
void softmax_kernel() {
    __shared__ float srow[T_];
    __shared__ float red[256];
    int bh = blockIdx.y, i = blockIdx.x;
    float* row = g_s + (size_t)bh * T_ * T_ + (size_t)i * T_;
    int len = i + 1;
    int tid = threadIdx.x;

    for (int j = tid; j < len; j += 256) srow[j] = row[j];
    __syncthreads();

    float m = -INFINITY;
    for (int j = tid; j < len; j += 256) m = fmaxf(m, srow[j]);
    red[tid] = m; __syncthreads();
    for (int s = 128; s > 0; s >>= 1) {
        if (tid < s) red[tid] = fmaxf(red[tid], red[tid + s]);
        __syncthreads();
    }
    m = red[0];
    __syncthreads();

    float ssum = 0.0f;
    for (int j = tid; j < len; j += 256) ssum += expf(srow[j] - m);
    red[tid] = ssum; __syncthreads();
    for (int s = 128; s > 0; s >>= 1) {
        if (tid < s) red[tid] += red[tid + s];
        __syncthreads();
    }
    float inv = 1.0f / red[0];

    bf16* outh = (bf16*)row;
    bf16* outl = outh + T_;
    for (int j = tid; j < len; j += 256) {
        float p = expf(srow[j] - m) * inv;
        splitb(p, outh[j], outl[j]);
    }
    int pad_end = ((i >> 7) + 1) << 7;
    bf16 z = __float2bfloat16(0.0f);
    for (int j = len + tid; j < pad_end; j += 256) { outh[j] = z; outl[j] = z; }
}

// merge heads + split: g_o [bh,T,D] -> attn hi/lo bf16 (aliased into g_qkv)
__global__ void merge_split_kernel(bf16* __restrict__ ah, bf16* __restrict__ al) {
    int row = blockIdx.x, h = blockIdx.y, d = threadIdx.x;
    int b = row >> 11, t = row & (T_ - 1);
    float v = g_o[((size_t)(b * H_ + h) * T_ + t) * D_ + d];
    size_t o = (size_t)row * C_ + h * D_ + d;
    splitb(v, ah[o], al[o]);
}

// ---------------------------------------------------------------------------
// launch
// ---------------------------------------------------------------------------
extern "C" void kernel_launch(void* const* d_in, const int* in_sizes, int n_in,
                              void* d_out, int out_size) {
    const float* x      = (const float*)d_in[0];
    const float* w_qkv  = (const float*)d_in[1];
    const float* w_proj = (const float*)d_in[2];
    const float* b_proj = (const float*)d_in[3];
    float* out = (float*)d_out;

    float* p_qkv;
    bf16 *p_xh, *p_xl, *p_wqh, *p_wql, *p_wph, *p_wpl;
    cudaGetSymbolAddress((void**)&p_qkv, g_qkv);
    cudaGetSymbolAddress((void**)&p_xh, g_xh);
    cudaGetSymbolAddress((void**)&p_xl, g_xl);
    cudaGetSymbolAddress((void**)&p_wqh, g_wqh);
    cudaGetSymbolAddress((void**)&p_wql, g_wql);
    cudaGetSymbolAddress((void**)&p_wph, g_wph);
    cudaGetSymbolAddress((void**)&p_wpl, g_wpl);

    // alias merged-attn split buffers into dead g_qkv storage
    bf16* p_ah = (bf16*)p_qkv;
    bf16* p_al = p_ah + (size_t)M_ * C_;

    cudaFuncSetAttribute(lin_gemm_kernel,
                         cudaFuncAttributeMaxDynamicSharedMemorySize, GEMM_SMEM);
    cudaFuncSetAttribute(score_gemm_kernel,
                         cudaFuncAttributeMaxDynamicSharedMemorySize, GEMM_SMEM);
    cudaFuncSetAttribute(av_gemm_kernel,
                         cudaFuncAttributeMaxDynamicSharedMemorySize, GEMM_SMEM);

    rope_table_kernel<<<T_, 64>>>();
    split_x_kernel<<<(M_ * C_) / 256, 256>>>(x);
    wtrans_kernel<<<dim3(N3_ / 32, C_ / 32), dim3(32, 8)>>>(w_qkv, p_wqh, p_wql, C_, N3_);
    wtrans_kernel<<<dim3(C_ / 32, C_ / 32), dim3(32, 8)>>>(w_proj, p_wph, p_wpl, C_, C_);

    // QKV: [8192,2048] @ [2048,6144]
    lin_gemm_kernel<<<dim3(N3_ / 128, M_ / 128), 256, GEMM_SMEM>>>(
        p_xh, p_xl, p_wqh, p_wql, p_qkv, N3_, C_, nullptr);

    rope_split_kernel<<<dim3(M_, H_), D_>>>();
    vtrans_kernel<<<dim3(T_ / 32, D_ / 32, BH_), dim3(32, 8)>>>();

    score_gemm_kernel<<<dim3(136, BH_), 256, GEMM_SMEM>>>();
    softmax_kernel<<<dim3(T_, BH_), 256>>>();
    av_gemm_kernel<<<dim3(16, BH_), 256, GEMM_SMEM>>>();

    merge_split_kernel<<<dim3(M_, H_), D_>>>(p_ah, p_al);

    // proj: [8192,2048] @ [2048,2048] + bias
    lin_gemm_kernel<<<dim3(C_ / 128, M_ / 128), 256, GEMM_SMEM>>>(
        p_ah, p_al, p_wph, p_wpl, out, C_, C_, b_proj);
}